// round 15
// baseline (speedup 1.0000x reference)
#include <cuda_runtime.h>
#include <cuda_fp16.h>
#include <cstdint>

#define BB 2
#define NN 2048
#define EE 1024
#define HH 16
#define DD 64
#define MM (BB*NN)

// Scratch: everything fp16 (same 10-bit mantissa as tf32 -> same accuracy).
__device__ __half g_Xh[MM*EE];          // x
__device__ __half g_Wh[4][EE*EE];       // Wq,Wk,Wv,Wo
__device__ __half g_Q[BB*HH*NN*DD];     // [b,h,n,d]
__device__ __half g_K[BB*HH*NN*DD];
__device__ __half g_V[BB*HH*NN*DD];
__device__ __half g_AOh[BB*NN*EE];      // attn out [b,n,e]

__device__ __forceinline__ void mma_f16(float* d, const uint32_t* a, const uint32_t* b) {
    asm volatile(
        "mma.sync.aligned.m16n8k16.row.col.f32.f16.f16.f32 "
        "{%0,%1,%2,%3}, {%4,%5,%6,%7}, {%8,%9}, {%0,%1,%2,%3};"
        : "+f"(d[0]), "+f"(d[1]), "+f"(d[2]), "+f"(d[3])
        : "r"(a[0]), "r"(a[1]), "r"(a[2]), "r"(a[3]), "r"(b[0]), "r"(b[1]));
}
__device__ __forceinline__ void ldsm4(uint32_t& r0, uint32_t& r1, uint32_t& r2,
                                      uint32_t& r3, uint32_t a) {
    asm volatile("ldmatrix.sync.aligned.m8n8.x4.shared.b16 {%0,%1,%2,%3}, [%4];"
        : "=r"(r0), "=r"(r1), "=r"(r2), "=r"(r3) : "r"(a));
}
__device__ __forceinline__ void ldsm4t(uint32_t& r0, uint32_t& r1, uint32_t& r2,
                                       uint32_t& r3, uint32_t a) {
    asm volatile("ldmatrix.sync.aligned.m8n8.x4.trans.shared.b16 {%0,%1,%2,%3}, [%4];"
        : "=r"(r0), "=r"(r1), "=r"(r2), "=r"(r3) : "r"(a));
}
__device__ __forceinline__ void cpa16(uint32_t s, const void* g) {
    asm volatile("cp.async.cg.shared.global [%0], [%1], 16;" :: "r"(s), "l"(g));
}
__device__ __forceinline__ void cp_commit() { asm volatile("cp.async.commit_group;"); }
template<int N> __device__ __forceinline__ void cp_wait() {
    asm volatile("cp.async.wait_group %0;" :: "n"(N));
}
__device__ __forceinline__ uint32_t pack_h2(float lo, float hi) {
    __half2 h = __floats2half2_rn(lo, hi);
    return *reinterpret_cast<uint32_t*>(&h);
}
__device__ __forceinline__ uint32_t ex2h2(uint32_t x) {   // 2 exps per MUFU op
    uint32_t r;
    asm("ex2.approx.f16x2 %0, %1;" : "=r"(r) : "r"(x));
    return r;
}
__device__ __forceinline__ __half2 u2h2(uint32_t u) {
    __half2 h; *reinterpret_cast<uint32_t*>(&h) = u; return h;
}

// ---------------------------------------------------------------------------
// Fused fp32 -> fp16 convert: x (1M float4) + 4 W's (256K float4 each).
// ---------------------------------------------------------------------------
#define NX4 (MM*EE/4)       // 1048576
#define NW4 (EE*EE/4)       // 262144
__global__ __launch_bounds__(256)
void conv_h(const float4* __restrict__ x,  const float4* __restrict__ w0,
            const float4* __restrict__ w1, const float4* __restrict__ w2,
            const float4* __restrict__ w3)
{
    int i = blockIdx.x * 256 + threadIdx.x;
    const float4* src; __half* dst; int off;
    if (i < NX4) { src = x; dst = g_Xh; off = i; }
    else {
        int k = i - NX4;
        int j = k >> 18;            // NW4 = 2^18
        off = k & (NW4 - 1);
        src = (j == 0) ? w0 : (j == 1) ? w1 : (j == 2) ? w2 : w3;
        dst = g_Wh[j];
    }
    float4 v = src[off];
    __half2* d2 = (__half2*)(dst + (size_t)off * 4);
    d2[0] = __floats2half2_rn(v.x, v.y);
    d2[1] = __floats2half2_rn(v.z, v.w);
}

// ---------------------------------------------------------------------------
// fp16 GEMM: C[4096][1024] = X @ W^T + bias. 128x128 tiles, BK=64, 512 thr
// (16 warps, 16x64 warp tile -> 32 acc regs), 3-stage cp.async, ldmatrix.
// 2 blocks/SM target: 110.6 KB smem x2 = 221 KB, 64 regs x 1024 thr = 64K.
// ---------------------------------------------------------------------------
#define GRS 72                    // smem row stride in halves (64 + 8 pad)
#define GSTH (128*GRS)            // 9216 halves per stage per matrix
#define GEMM_SMEM (6*GSTH*2)      // 110592 B

__global__ __launch_bounds__(512, 2)
void gemm_h(const float* __restrict__ b0p, const float* __restrict__ b1p,
            const float* __restrict__ b2p, const float* __restrict__ b3p,
            float* __restrict__ outp, int target)
{
    const int tgt = (target < 0) ? (int)blockIdx.z : target;
    const __half* __restrict__ X = (tgt == 3) ? g_AOh : g_Xh;
    const __half* __restrict__ W = g_Wh[tgt];
    const float* __restrict__ bias = (tgt == 0) ? b0p : (tgt == 1) ? b1p : (tgt == 2) ? b2p : b3p;

    extern __shared__ __align__(16) __half smh[];
    const uint32_t sbA = (uint32_t)__cvta_generic_to_shared(smh);
    const uint32_t sbW = sbA + 3 * GSTH * 2;

    const int tid = threadIdx.x;
    const int warp = tid >> 5, lane = tid & 31;
    const int g = lane >> 2, t = lane & 3;
    const int m0 = blockIdx.y * 128, n0 = blockIdx.x * 128;
    const int wm = (warp & 7) * 16;        // 8 m-slots of 16
    const int wn = (warp >> 3) * 64;       // 2 n-slots of 64

    // ldmatrix per-lane address components
    const int a_row = wm + (lane & 7) + ((lane >> 3) & 1) * 8;
    const int a_k   = (lane >> 4) * 8;                          // + ks*16
    const int b_row = wn + (lane & 7) + (lane >> 4) * 8;        // + ntp*16
    const int b_k   = ((lane >> 3) & 1) * 8;                    // + ks*16

    float acc[8][4];
    #pragma unroll
    for (int j = 0; j < 8; j++)
        #pragma unroll
        for (int k = 0; k < 4; k++) acc[j][k] = 0.f;

    // per stage per matrix: 128 rows x 64 halves = 1024 chunks of 16B; 2/thread
    auto issue = [&](int s, int kk) {
        #pragma unroll
        for (int i = 0; i < 2; i++) {
            const int idx = tid + i * 512;
            const int r = idx >> 3, c = (idx & 7) * 8;
            cpa16(sbA + (uint32_t)(s * GSTH + r * GRS + c) * 2,
                  X + (size_t)(m0 + r) * EE + kk * 64 + c);
            cpa16(sbW + (uint32_t)(s * GSTH + r * GRS + c) * 2,
                  W + (size_t)(n0 + r) * EE + kk * 64 + c);
        }
        cp_commit();
    };

    issue(0, 0);
    issue(1, 1);

    for (int kt = 0; kt < 16; kt++) {
        const int buf = kt % 3;
        if (kt < 15) cp_wait<1>(); else cp_wait<0>();
        __syncthreads();
        if (kt + 2 < 16) issue((kt + 2) % 3, kt + 2);

        const uint32_t abase = sbA + (uint32_t)(buf * GSTH) * 2;
        const uint32_t wbase = sbW + (uint32_t)(buf * GSTH) * 2;
        #pragma unroll
        for (int ks = 0; ks < 4; ks++) {
            uint32_t af[4];
            ldsm4(af[0], af[1], af[2], af[3],
                  abase + (uint32_t)(a_row * GRS + ks * 16 + a_k) * 2);
            #pragma unroll
            for (int ntp = 0; ntp < 4; ntp++) {
                uint32_t b0, b1, b2, b3;
                ldsm4(b0, b1, b2, b3,
                      wbase + (uint32_t)((b_row + ntp * 16) * GRS + ks * 16 + b_k) * 2);
                uint32_t bfa[2] = {b0, b1}, bfb[2] = {b2, b3};
                mma_f16(acc[2 * ntp],     af, bfa);
                mma_f16(acc[2 * ntp + 1], af, bfb);
            }
        }
        // no trailing sync: next iter's top barrier fences the stage reuse
    }

    __half* dstQKV = (tgt == 0) ? g_Q : (tgt == 1) ? g_K : g_V;
    #pragma unroll
    for (int nt = 0; nt < 8; nt++) {
        const int rbase = m0 + wm + g;
        const int cbase = n0 + wn + nt * 8 + 2 * t;
        #pragma unroll
        for (int hh = 0; hh < 2; hh++) {
            const int m = rbase + hh * 8;
            const float v0 = acc[nt][2 * hh + 0] + bias[cbase + 0];
            const float v1 = acc[nt][2 * hh + 1] + bias[cbase + 1];
            if (tgt == 3) {
                outp[m * EE + cbase + 0] = v0;
                outp[m * EE + cbase + 1] = v1;
            } else {
                const int b = m >> 11;
                const int n = m & (NN - 1);
                const int h = cbase >> 6;
                const int d = cbase & (DD - 1);
                *(__half2*)&dstQKV[((b * HH + h) * NN + n) * DD + d] =
                    __floats2half2_rn(v0, v1);
            }
        }
    }
}

// ---------------------------------------------------------------------------
// Flash attention (unchanged from R12): fp16 m16n8k16, 64-key tiles,
// 3-stage cp.async, one barrier/tile, fp16x2 exp.
// ---------------------------------------------------------------------------
#define KSTAGE_H 4608
#define VBASE_H  13824
#define PBASE_H  27648
#define ATTN_SMEM ((PBASE_H + 4608) * 2)

__global__ __launch_bounds__(128, 3)
void attn_h()
{
    extern __shared__ __align__(16) __half smh[];
    uint32_t* smw_mut = (uint32_t*)smh;
    const uint32_t sb = (uint32_t)__cvta_generic_to_shared(smh);

    const int bh = blockIdx.x;
    const int q0 = blockIdx.y * 64;
    const int tid = threadIdx.x, warp = tid >> 5, lane = tid & 31;
    const int g = lane >> 2, t = lane & 3;
    const float L2E = 1.4426950408889634f;

    const __half* __restrict__ Qp = g_Q + (size_t)bh * NN * DD;
    const __half* __restrict__ Kp = g_K + (size_t)bh * NN * DD;
    const __half* __restrict__ Vp = g_V + (size_t)bh * NN * DD;

    auto issueK = [&](int s, int kk) {
        const uint32_t off = sb + (uint32_t)(s * KSTAGE_H) * 2;
        #pragma unroll
        for (int i = 0; i < 4; i++) {
            const int idx = tid + i * 128;
            const int r = idx >> 3, c = (idx & 7) * 8;
            cpa16(off + (uint32_t)(r * 72 + c) * 2, Kp + (size_t)(kk * 64 + r) * DD + c);
        }
    };
    auto issueV = [&](int s, int kk) {
        const uint32_t off = sb + (uint32_t)(VBASE_H + s * KSTAGE_H) * 2;
        #pragma unroll
        for (int i = 0; i < 4; i++) {
            const int idx = tid + i * 128;
            const int r = idx >> 3, c = (idx & 7) * 8;
            cpa16(off + (uint32_t)(r * 72 + c) * 2, Vp + (size_t)(kk * 64 + r) * DD + c);
        }
    };

    {
        const uint32_t qoff = sb + (uint32_t)PBASE_H * 2;
        #pragma unroll
        for (int i = 0; i < 4; i++) {
            const int idx = tid + i * 128;
            const int r = idx >> 3, c = (idx & 7) * 8;
            cpa16(qoff + (uint32_t)(r * 72 + c) * 2, Qp + (size_t)(q0 + r) * DD + c);
        }
        cp_commit();
        issueK(0, 0); issueV(0, 0); cp_commit();
        issueK(1, 1); issueV(1, 1); cp_commit();
    }
    cp_wait<2>();
    __syncthreads();

    const int a_row = warp * 16 + (lane & 7) + ((lane >> 3) & 1) * 8;
    const int a_k   = (lane >> 4) * 8;
    uint32_t qa[4][4];
    {
        const uint32_t qbase = sb + (uint32_t)PBASE_H * 2;
        #pragma unroll
        for (int ks = 0; ks < 4; ks++)
            ldsm4(qa[ks][0], qa[ks][1], qa[ks][2], qa[ks][3],
                  qbase + (uint32_t)(a_row * 72 + ks * 16 + a_k) * 2);
    }
    __syncthreads();

    float O[8][4];
    #pragma unroll
    for (int i = 0; i < 8; i++)
        #pragma unroll
        for (int j = 0; j < 4; j++) O[i][j] = 0.f;
    float m1 = -1e30f, m2 = -1e30f, l1 = 0.f, l2 = 0.f;

    uint32_t* const Pw = smw_mut + (PBASE_H / 2) + warp * 576;
    const uint32_t pbase = sb + (uint32_t)(PBASE_H + warp * 1152) * 2;

    const int kb_row = (lane & 7) + (lane >> 4) * 8;
    const int kb_k   = ((lane >> 3) & 1) * 8;
    const int pa_row = (lane & 7) + ((lane >> 3) & 1) * 8;
    const int pa_k   = (lane >> 4) * 8;
    const int llo = lane & 7, sel = lane >> 3;
    const uint32_t vlane = (uint32_t)(((sel & 1) * 8 + llo) * 72 + (sel >> 1) * 8) * 2;

    for (int kt = 0; kt < 32; kt++) {
        const int buf = kt % 3;
        if (kt < 31) cp_wait<1>(); else cp_wait<0>();
        __syncthreads();
        if (kt + 2 < 32) { issueK((kt + 2) % 3, kt + 2); issueV((kt + 2) % 3, kt + 2); cp_commit(); }

        const uint32_t kbase  = sb + (uint32_t)(buf * KSTAGE_H) * 2;
        const uint32_t vstage = sb + (uint32_t)(VBASE_H + buf * KSTAGE_H) * 2;

        float S[8][4];
        #pragma unroll
        for (int i = 0; i < 8; i++)
            #pragma unroll
            for (int j = 0; j < 4; j++) S[i][j] = 0.f;

        #pragma unroll
        for (int ks = 0; ks < 4; ks++) {
            #pragma unroll
            for (int ntp = 0; ntp < 4; ntp++) {
                uint32_t b0, b1, b2, b3;
                ldsm4(b0, b1, b2, b3,
                      kbase + (uint32_t)((kb_row + ntp * 16) * 72 + ks * 16 + kb_k) * 2);
                uint32_t bfa[2] = {b0, b1}, bfb[2] = {b2, b3};
                mma_f16(S[2 * ntp],     qa[ks], bfa);
                mma_f16(S[2 * ntp + 1], qa[ks], bfb);
            }
        }

        float rmax1 = -1e30f, rmax2 = -1e30f;
        #pragma unroll
        for (int nt = 0; nt < 8; nt++) {
            rmax1 = fmaxf(rmax1, fmaxf(S[nt][0], S[nt][1]));
            rmax2 = fmaxf(rmax2, fmaxf(S[nt][2], S[nt][3]));
        }
        rmax1 = fmaxf(rmax1, __shfl_xor_sync(0xffffffff, rmax1, 1));
        rmax1 = fmaxf(rmax1, __shfl_xor_sync(0xffffffff, rmax1, 2));
        rmax2 = fmaxf(rmax2, __shfl_xor_sync(0xffffffff, rmax2, 1));
        rmax2 = fmaxf(rmax2, __shfl_xor_sync(0xffffffff, rmax2, 2));

        const float mn1 = fmaxf(m1, rmax1);
        const float mn2 = fmaxf(m2, rmax2);
        const float cr1 = __expf(m1 - mn1);
        const float cr2 = __expf(m2 - mn2);
        const float bb1 = mn1 * L2E;
        const float bb2 = mn2 * L2E;

        uint32_t p1[8], p2[8];
        __half2 hs1 = __floats2half2_rn(0.f, 0.f);
        __half2 hs2 = hs1;
        #pragma unroll
        for (int nt = 0; nt < 8; nt++) {
            uint32_t u1 = pack_h2(fmaf(S[nt][0], L2E, -bb1), fmaf(S[nt][1], L2E, -bb1));
            uint32_t u2 = pack_h2(fmaf(S[nt][2], L2E, -bb2), fmaf(S[nt][3], L2E, -bb2));
            p1[nt] = ex2h2(u1);
            p2[nt] = ex2h2(u2);
            hs1 = __hadd2(hs1, u2h2(p1[nt]));
            hs2 = __hadd2(hs2, u2h2(p2[nt]));
        }
        float rs1 = __low2float(hs1) + __high2float(hs1);
        float rs2 = __low2float(hs2) + __high2float(hs2);
        rs1 += __shfl_xor_sync(0xffffffff, rs1, 1);
        rs1 += __shfl_xor_sync(0xffffffff, rs1, 2);
        rs2 += __shfl_xor_sync(0xffffffff, rs2, 1);
        rs2 += __shfl_xor_sync(0xffffffff, rs2, 2);

        l1 = l1 * cr1 + rs1;
        l2 = l2 * cr2 + rs2;
        m1 = mn1; m2 = mn2;

        if (cr1 < 1.0f || cr2 < 1.0f) {
            #pragma unroll
            for (int nt = 0; nt < 8; nt++) {
                O[nt][0] *= cr1; O[nt][1] *= cr1;
                O[nt][2] *= cr2; O[nt][3] *= cr2;
            }
        }

        __syncwarp();
        #pragma unroll
        for (int nt = 0; nt < 8; nt++) {
            Pw[g * 36 + nt * 4 + t]       = p1[nt];
            Pw[(g + 8) * 36 + nt * 4 + t] = p2[nt];
        }
        __syncwarp();

        #pragma unroll
        for (int ks = 0; ks < 4; ks++) {
            uint32_t pa[4];
            ldsm4(pa[0], pa[1], pa[2], pa[3],
                  pbase + (uint32_t)(pa_row * 72 + ks * 16 + pa_k) * 2);
            #pragma unroll
            for (int p = 0; p < 4; p++) {
                uint32_t b0, b1, b2, b3;
                ldsm4t(b0, b1, b2, b3, vstage + vlane + ks * 2304 + p * 32);
                uint32_t bA[2] = {b0, b1}, bB[2] = {b2, b3};
                mma_f16(O[2 * p],     pa, bA);
                mma_f16(O[2 * p + 1], pa, bB);
            }
        }
    }

    const int b = bh / HH, h = bh % HH;
    const int q1 = q0 + warp * 16 + g;
    const int q2 = q1 + 8;
    const float i1 = 1.0f / (l1 * 32.0f);
    const float i2 = 1.0f / (l2 * 32.0f);
    __half2* d1 = (__half2*)(g_AOh + ((size_t)(b * NN + q1)) * EE + h * DD);
    __half2* d2 = (__half2*)(g_AOh + ((size_t)(b * NN + q2)) * EE + h * DD);
    #pragma unroll
    for (int nt = 0; nt < 8; nt++) {
        d1[nt * 4 + t] = __floats2half2_rn(O[nt][0] * i1, O[nt][1] * i1);
        d2[nt * 4 + t] = __floats2half2_rn(O[nt][2] * i2, O[nt][3] * i2);
    }
}

// ---------------------------------------------------------------------------
extern "C" void kernel_launch(void* const* d_in, const int* in_sizes, int n_in,
                              void* d_out, int out_size)
{
    const float* x  = (const float*)d_in[0];
    const float* Wq = (const float*)d_in[1];
    const float* bq = (const float*)d_in[2];
    const float* Wk = (const float*)d_in[3];
    const float* bk = (const float*)d_in[4];
    const float* Wv = (const float*)d_in[5];
    const float* bv = (const float*)d_in[6];
    const float* Wo = (const float*)d_in[7];
    const float* bo = (const float*)d_in[8];
    float* out = (float*)d_out;

    cudaFuncSetAttribute(gemm_h, cudaFuncAttributeMaxDynamicSharedMemorySize, GEMM_SMEM);
    cudaFuncSetAttribute(attn_h, cudaFuncAttributeMaxDynamicSharedMemorySize, ATTN_SMEM);

    const int total4 = NX4 + 4 * NW4;     // 2097152
    conv_h<<<total4 / 256, 256>>>((const float4*)x, (const float4*)Wq,
                                  (const float4*)Wk, (const float4*)Wv,
                                  (const float4*)Wo);

    gemm_h<<<dim3(EE/128, MM/128, 3), 512, GEMM_SMEM>>>(bq, bk, bv, bo, nullptr, -1);
    attn_h<<<dim3(BB*HH, NN/64), 128, ATTN_SMEM>>>();
    gemm_h<<<dim3(EE/128, MM/128, 1), 512, GEMM_SMEM>>>(bq, bk, bv, bo, out, 3);
}

// round 16
// speedup vs baseline: 1.0847x; 1.0847x over previous
#include <cuda_runtime.h>
#include <cuda_fp16.h>
#include <cstdint>

#define BB 2
#define NN 2048
#define EE 1024
#define HH 16
#define DD 64
#define MM (BB*NN)

// Scratch: everything fp16 (same 10-bit mantissa as tf32 -> same accuracy).
__device__ __half g_Xh[MM*EE];          // x
__device__ __half g_Wh[4][EE*EE];       // Wq,Wk,Wv,Wo
__device__ __half g_Q[BB*HH*NN*DD];     // [b,h,n,d]
__device__ __half g_K[BB*HH*NN*DD];
__device__ __half g_V[BB*HH*NN*DD];
__device__ __half g_AOh[BB*NN*EE];      // attn out [b,n,e]

__device__ __forceinline__ void mma_f16(float* d, const uint32_t* a, const uint32_t* b) {
    asm volatile(
        "mma.sync.aligned.m16n8k16.row.col.f32.f16.f16.f32 "
        "{%0,%1,%2,%3}, {%4,%5,%6,%7}, {%8,%9}, {%0,%1,%2,%3};"
        : "+f"(d[0]), "+f"(d[1]), "+f"(d[2]), "+f"(d[3])
        : "r"(a[0]), "r"(a[1]), "r"(a[2]), "r"(a[3]), "r"(b[0]), "r"(b[1]));
}
__device__ __forceinline__ void ldsm4(uint32_t& r0, uint32_t& r1, uint32_t& r2,
                                      uint32_t& r3, uint32_t a) {
    asm volatile("ldmatrix.sync.aligned.m8n8.x4.shared.b16 {%0,%1,%2,%3}, [%4];"
        : "=r"(r0), "=r"(r1), "=r"(r2), "=r"(r3) : "r"(a));
}
__device__ __forceinline__ void ldsm4t(uint32_t& r0, uint32_t& r1, uint32_t& r2,
                                       uint32_t& r3, uint32_t a) {
    asm volatile("ldmatrix.sync.aligned.m8n8.x4.trans.shared.b16 {%0,%1,%2,%3}, [%4];"
        : "=r"(r0), "=r"(r1), "=r"(r2), "=r"(r3) : "r"(a));
}
__device__ __forceinline__ void cpa16(uint32_t s, const void* g) {
    asm volatile("cp.async.cg.shared.global [%0], [%1], 16;" :: "r"(s), "l"(g));
}
__device__ __forceinline__ void cp_commit() { asm volatile("cp.async.commit_group;"); }
template<int N> __device__ __forceinline__ void cp_wait() {
    asm volatile("cp.async.wait_group %0;" :: "n"(N));
}
__device__ __forceinline__ uint32_t pack_h2(float lo, float hi) {
    __half2 h = __floats2half2_rn(lo, hi);
    return *reinterpret_cast<uint32_t*>(&h);
}
__device__ __forceinline__ uint32_t ex2h2(uint32_t x) {   // 2 exps per MUFU op
    uint32_t r;
    asm("ex2.approx.f16x2 %0, %1;" : "=r"(r) : "r"(x));
    return r;
}
__device__ __forceinline__ __half2 u2h2(uint32_t u) {
    __half2 h; *reinterpret_cast<uint32_t*>(&h) = u; return h;
}

// ---------------------------------------------------------------------------
// Fused fp32 -> fp16 convert: x (1M float4) + 4 W's (256K float4 each).
// ---------------------------------------------------------------------------
#define NX4 (MM*EE/4)       // 1048576
#define NW4 (EE*EE/4)       // 262144
__global__ __launch_bounds__(256)
void conv_h(const float4* __restrict__ x,  const float4* __restrict__ w0,
            const float4* __restrict__ w1, const float4* __restrict__ w2,
            const float4* __restrict__ w3)
{
    int i = blockIdx.x * 256 + threadIdx.x;
    const float4* src; __half* dst; int off;
    if (i < NX4) { src = x; dst = g_Xh; off = i; }
    else {
        int k = i - NX4;
        int j = k >> 18;            // NW4 = 2^18
        off = k & (NW4 - 1);
        src = (j == 0) ? w0 : (j == 1) ? w1 : (j == 2) ? w2 : w3;
        dst = g_Wh[j];
    }
    float4 v = src[off];
    __half2* d2 = (__half2*)(dst + (size_t)off * 4);
    d2[0] = __floats2half2_rn(v.x, v.y);
    d2[1] = __floats2half2_rn(v.z, v.w);
}

// ---------------------------------------------------------------------------
// fp16 GEMM (R12 version — best measured): 128x128 tiles, BK=64, 256 thr,
// 8 warps of 32x64, 3-stage cp.async, ldmatrix, single sync per k-iter.
// ---------------------------------------------------------------------------
#define GRS 72                    // smem row stride in halves (64 + 8 pad)
#define GSTH (128*GRS)            // 9216 halves per stage per matrix
#define GEMM_SMEM (6*GSTH*2)      // 110592 B

__global__ __launch_bounds__(256)
void gemm_h(const float* __restrict__ b0p, const float* __restrict__ b1p,
            const float* __restrict__ b2p, const float* __restrict__ b3p,
            float* __restrict__ outp, int target)
{
    const int tgt = (target < 0) ? (int)blockIdx.z : target;
    const __half* __restrict__ X = (tgt == 3) ? g_AOh : g_Xh;
    const __half* __restrict__ W = g_Wh[tgt];
    const float* __restrict__ bias = (tgt == 0) ? b0p : (tgt == 1) ? b1p : (tgt == 2) ? b2p : b3p;

    extern __shared__ __align__(16) __half smh[];
    const uint32_t sbA = (uint32_t)__cvta_generic_to_shared(smh);
    const uint32_t sbW = sbA + 3 * GSTH * 2;

    const int tid = threadIdx.x;
    const int warp = tid >> 5, lane = tid & 31;
    const int g = lane >> 2, t = lane & 3;
    const int m0 = blockIdx.y * 128, n0 = blockIdx.x * 128;
    const int wm = (warp >> 1) * 32, wn = (warp & 1) * 64;

    // ldmatrix per-lane address components
    const int a_row = wm + (lane & 7) + ((lane >> 3) & 1) * 8;  // + mi*16
    const int a_k   = (lane >> 4) * 8;                          // + ks*16
    const int b_row = wn + (lane & 7) + (lane >> 4) * 8;        // + ntp*16
    const int b_k   = ((lane >> 3) & 1) * 8;                    // + ks*16

    float acc[2][8][4];
    #pragma unroll
    for (int i = 0; i < 2; i++)
        #pragma unroll
        for (int j = 0; j < 8; j++)
            #pragma unroll
            for (int k = 0; k < 4; k++) acc[i][j][k] = 0.f;

    // per stage per matrix: 128 rows x 64 halves = 1024 chunks of 16B; 4/thread
    auto issue = [&](int s, int kk) {
        #pragma unroll
        for (int i = 0; i < 4; i++) {
            const int idx = tid + i * 256;
            const int r = idx >> 3, c = (idx & 7) * 8;
            cpa16(sbA + (uint32_t)(s * GSTH + r * GRS + c) * 2,
                  X + (size_t)(m0 + r) * EE + kk * 64 + c);
            cpa16(sbW + (uint32_t)(s * GSTH + r * GRS + c) * 2,
                  W + (size_t)(n0 + r) * EE + kk * 64 + c);
        }
        cp_commit();
    };

    issue(0, 0);
    issue(1, 1);

    for (int kt = 0; kt < 16; kt++) {
        const int buf = kt % 3;
        if (kt < 15) cp_wait<1>(); else cp_wait<0>();
        __syncthreads();
        if (kt + 2 < 16) issue((kt + 2) % 3, kt + 2);

        const uint32_t abase = sbA + (uint32_t)(buf * GSTH) * 2;
        const uint32_t wbase = sbW + (uint32_t)(buf * GSTH) * 2;
        #pragma unroll
        for (int ks = 0; ks < 4; ks++) {
            uint32_t af[2][4];
            ldsm4(af[0][0], af[0][1], af[0][2], af[0][3],
                  abase + (uint32_t)(a_row * GRS + ks * 16 + a_k) * 2);
            ldsm4(af[1][0], af[1][1], af[1][2], af[1][3],
                  abase + (uint32_t)((a_row + 16) * GRS + ks * 16 + a_k) * 2);
            #pragma unroll
            for (int ntp = 0; ntp < 4; ntp++) {
                uint32_t b0, b1, b2, b3;
                ldsm4(b0, b1, b2, b3,
                      wbase + (uint32_t)((b_row + ntp * 16) * GRS + ks * 16 + b_k) * 2);
                uint32_t bfa[2] = {b0, b1}, bfb[2] = {b2, b3};
                mma_f16(acc[0][2 * ntp],     af[0], bfa);
                mma_f16(acc[1][2 * ntp],     af[1], bfa);
                mma_f16(acc[0][2 * ntp + 1], af[0], bfb);
                mma_f16(acc[1][2 * ntp + 1], af[1], bfb);
            }
        }
        // no trailing sync: next iter's top barrier fences the stage reuse
    }

    __half* dstQKV = (tgt == 0) ? g_Q : (tgt == 1) ? g_K : g_V;
    #pragma unroll
    for (int mi = 0; mi < 2; mi++) {
        #pragma unroll
        for (int nt = 0; nt < 8; nt++) {
            const int rbase = m0 + wm + mi * 16 + g;
            const int cbase = n0 + wn + nt * 8 + 2 * t;
            #pragma unroll
            for (int hh = 0; hh < 2; hh++) {
                const int m = rbase + hh * 8;
                const float v0 = acc[mi][nt][2 * hh + 0] + bias[cbase + 0];
                const float v1 = acc[mi][nt][2 * hh + 1] + bias[cbase + 1];
                if (tgt == 3) {
                    outp[m * EE + cbase + 0] = v0;
                    outp[m * EE + cbase + 1] = v1;
                } else {
                    const int b = m >> 11;
                    const int n = m & (NN - 1);
                    const int h = cbase >> 6;
                    const int d = cbase & (DD - 1);
                    *(__half2*)&dstQKV[((b * HH + h) * NN + n) * DD + d] =
                        __floats2half2_rn(v0, v1);
                }
            }
        }
    }
}

// ---------------------------------------------------------------------------
// Flash attention: fp16 m16n8k16, 64-key tiles, 3-stage cp.async,
// one barrier/tile, fp16x2 exp, REGISTER P-reuse (C-frag == A-frag; no smem
// round trip for P). grid (B*H, N/64), block 128 (4 warps).
// smem (halves): K 3x4608 @0; V 3x4608 @13824; Q staging 4608 @27648.
// ---------------------------------------------------------------------------
#define KSTAGE_H 4608
#define VBASE_H  13824
#define PBASE_H  27648
#define ATTN_SMEM ((PBASE_H + 4608) * 2)   // 64512 B

__global__ __launch_bounds__(128, 3)
void attn_h()
{
    extern __shared__ __align__(16) __half smh[];
    const uint32_t sb = (uint32_t)__cvta_generic_to_shared(smh);

    const int bh = blockIdx.x;
    const int q0 = blockIdx.y * 64;
    const int tid = threadIdx.x, warp = tid >> 5, lane = tid & 31;
    const int g = lane >> 2, t = lane & 3;
    const float L2E = 1.4426950408889634f;

    const __half* __restrict__ Qp = g_Q + (size_t)bh * NN * DD;
    const __half* __restrict__ Kp = g_K + (size_t)bh * NN * DD;
    const __half* __restrict__ Vp = g_V + (size_t)bh * NN * DD;

    auto issueK = [&](int s, int kk) {
        const uint32_t off = sb + (uint32_t)(s * KSTAGE_H) * 2;
        #pragma unroll
        for (int i = 0; i < 4; i++) {
            const int idx = tid + i * 128;
            const int r = idx >> 3, c = (idx & 7) * 8;
            cpa16(off + (uint32_t)(r * 72 + c) * 2, Kp + (size_t)(kk * 64 + r) * DD + c);
        }
    };
    auto issueV = [&](int s, int kk) {
        const uint32_t off = sb + (uint32_t)(VBASE_H + s * KSTAGE_H) * 2;
        #pragma unroll
        for (int i = 0; i < 4; i++) {
            const int idx = tid + i * 128;
            const int r = idx >> 3, c = (idx & 7) * 8;
            cpa16(off + (uint32_t)(r * 72 + c) * 2, Vp + (size_t)(kk * 64 + r) * DD + c);
        }
    };

    // Prologue: Q -> staging region; tiles 0,1 -> stages 0,1
    {
        const uint32_t qoff = sb + (uint32_t)PBASE_H * 2;
        #pragma unroll
        for (int i = 0; i < 4; i++) {
            const int idx = tid + i * 128;
            const int r = idx >> 3, c = (idx & 7) * 8;
            cpa16(qoff + (uint32_t)(r * 72 + c) * 2, Qp + (size_t)(q0 + r) * DD + c);
        }
        cp_commit();
        issueK(0, 0); issueV(0, 0); cp_commit();
        issueK(1, 1); issueV(1, 1); cp_commit();
    }
    cp_wait<2>();
    __syncthreads();

    // hoist Q a-fragments via ldmatrix (4 k-steps of 16)
    const int a_row = warp * 16 + (lane & 7) + ((lane >> 3) & 1) * 8;
    const int a_k   = (lane >> 4) * 8;
    uint32_t qa[4][4];
    {
        const uint32_t qbase = sb + (uint32_t)PBASE_H * 2;
        #pragma unroll
        for (int ks = 0; ks < 4; ks++)
            ldsm4(qa[ks][0], qa[ks][1], qa[ks][2], qa[ks][3],
                  qbase + (uint32_t)(a_row * 72 + ks * 16 + a_k) * 2);
    }
    __syncthreads();

    float O[8][4];
    #pragma unroll
    for (int i = 0; i < 8; i++)
        #pragma unroll
        for (int j = 0; j < 4; j++) O[i][j] = 0.f;
    float m1 = -1e30f, m2 = -1e30f, l1 = 0.f, l2 = 0.f;

    // ldmatrix lane address components
    const int kb_row = (lane & 7) + (lane >> 4) * 8;        // + ntp*16 (K b-frags)
    const int kb_k   = ((lane >> 3) & 1) * 8;               // + ks*16
    const int llo = lane & 7, sel = lane >> 3;
    const uint32_t vlane = (uint32_t)(((sel & 1) * 8 + llo) * 72 + (sel >> 1) * 8) * 2;

    for (int kt = 0; kt < 32; kt++) {
        const int buf = kt % 3;
        if (kt < 31) cp_wait<1>(); else cp_wait<0>();
        __syncthreads();     // the ONLY block barrier per tile
        if (kt + 2 < 32) { issueK((kt + 2) % 3, kt + 2); issueV((kt + 2) % 3, kt + 2); cp_commit(); }

        const uint32_t kbase  = sb + (uint32_t)(buf * KSTAGE_H) * 2;
        const uint32_t vstage = sb + (uint32_t)(VBASE_H + buf * KSTAGE_H) * 2;

        // S = Q K^T  (16 x 64 per warp), k-steps of 16
        float S[8][4];
        #pragma unroll
        for (int i = 0; i < 8; i++)
            #pragma unroll
            for (int j = 0; j < 4; j++) S[i][j] = 0.f;

        #pragma unroll
        for (int ks = 0; ks < 4; ks++) {
            #pragma unroll
            for (int ntp = 0; ntp < 4; ntp++) {
                uint32_t b0, b1, b2, b3;
                ldsm4(b0, b1, b2, b3,
                      kbase + (uint32_t)((kb_row + ntp * 16) * 72 + ks * 16 + kb_k) * 2);
                uint32_t bfa[2] = {b0, b1}, bfb[2] = {b2, b3};
                mma_f16(S[2 * ntp],     qa[ks], bfa);
                mma_f16(S[2 * ntp + 1], qa[ks], bfb);
            }
        }

        // online softmax (exp in fp16x2)
        float rmax1 = -1e30f, rmax2 = -1e30f;
        #pragma unroll
        for (int nt = 0; nt < 8; nt++) {
            rmax1 = fmaxf(rmax1, fmaxf(S[nt][0], S[nt][1]));
            rmax2 = fmaxf(rmax2, fmaxf(S[nt][2], S[nt][3]));
        }
        rmax1 = fmaxf(rmax1, __shfl_xor_sync(0xffffffff, rmax1, 1));
        rmax1 = fmaxf(rmax1, __shfl_xor_sync(0xffffffff, rmax1, 2));
        rmax2 = fmaxf(rmax2, __shfl_xor_sync(0xffffffff, rmax2, 1));
        rmax2 = fmaxf(rmax2, __shfl_xor_sync(0xffffffff, rmax2, 2));

        const float mn1 = fmaxf(m1, rmax1);
        const float mn2 = fmaxf(m2, rmax2);
        const float cr1 = __expf(m1 - mn1);
        const float cr2 = __expf(m2 - mn2);
        const float bb1 = mn1 * L2E;
        const float bb2 = mn2 * L2E;

        uint32_t p1[8], p2[8];
        __half2 hs1 = __floats2half2_rn(0.f, 0.f);
        __half2 hs2 = hs1;
        #pragma unroll
        for (int nt = 0; nt < 8; nt++) {
            uint32_t u1 = pack_h2(fmaf(S[nt][0], L2E, -bb1), fmaf(S[nt][1], L2E, -bb1));
            uint32_t u2 = pack_h2(fmaf(S[nt][2], L2E, -bb2), fmaf(S[nt][3], L2E, -bb2));
            p1[nt] = ex2h2(u1);
            p2[nt] = ex2h2(u2);
            hs1 = __hadd2(hs1, u2h2(p1[nt]));
            hs2 = __hadd2(hs2, u2h2(p2[nt]));
        }
        float rs1 = __low2float(hs1) + __high2float(hs1);
        float rs2 = __low2float(hs2) + __high2float(hs2);
        rs1 += __shfl_xor_sync(0xffffffff, rs1, 1);
        rs1 += __shfl_xor_sync(0xffffffff, rs1, 2);
        rs2 += __shfl_xor_sync(0xffffffff, rs2, 1);
        rs2 += __shfl_xor_sync(0xffffffff, rs2, 2);

        l1 = l1 * cr1 + rs1;
        l2 = l2 * cr2 + rs2;
        m1 = mn1; m2 = mn2;

        if (cr1 < 1.0f || cr2 < 1.0f) {      // skip rescale when max unchanged
            #pragma unroll
            for (int nt = 0; nt < 8; nt++) {
                O[nt][0] *= cr1; O[nt][1] *= cr1;
                O[nt][2] *= cr2; O[nt][3] *= cr2;
            }
        }

        // O += P V  — P a-frags DIRECTLY from the packed exp registers:
        // C-fragment (rows g/g+8, cols nt*8+2t..) == A-fragment layout, so
        // pa(ks) = {p1[2ks], p2[2ks], p1[2ks+1], p2[2ks+1]}. No smem, no sync.
        #pragma unroll
        for (int ks = 0; ks < 4; ks++) {
            uint32_t pa[4] = { p1[2 * ks], p2[2 * ks], p1[2 * ks + 1], p2[2 * ks + 1] };
            #pragma unroll
            for (int p = 0; p < 4; p++) {
                uint32_t b0, b1, b2, b3;
                ldsm4t(b0, b1, b2, b3, vstage + vlane + ks * 2304 + p * 32);
                uint32_t bA[2] = {b0, b1}, bB[2] = {b2, b3};
                mma_f16(O[2 * p],     pa, bA);
                mma_f16(O[2 * p + 1], pa, bB);
            }
        }
    }

    // epilogue: softmax norm + reference's /sqrt(E)=32; write fp16
    const int b = bh / HH, h = bh % HH;
    const int q1 = q0 + warp * 16 + g;
    const int q2 = q1 + 8;
    const float i1 = 1.0f / (l1 * 32.0f);
    const float i2 = 1.0f / (l2 * 32.0f);
    __half2* d1 = (__half2*)(g_AOh + ((size_t)(b * NN + q1)) * EE + h * DD);
    __half2* d2 = (__half2*)(g_AOh + ((size_t)(b * NN + q2)) * EE + h * DD);
    #pragma unroll
    for (int nt = 0; nt < 8; nt++) {
        d1[nt * 4 + t] = __floats2half2_rn(O[nt][0] * i1, O[nt][1] * i1);
        d2[nt * 4 + t] = __floats2half2_rn(O[nt][2] * i2, O[nt][3] * i2);
    }
}

// ---------------------------------------------------------------------------
extern "C" void kernel_launch(void* const* d_in, const int* in_sizes, int n_in,
                              void* d_out, int out_size)
{
    const float* x  = (const float*)d_in[0];
    const float* Wq = (const float*)d_in[1];
    const float* bq = (const float*)d_in[2];
    const float* Wk = (const float*)d_in[3];
    const float* bk = (const float*)d_in[4];
    const float* Wv = (const float*)d_in[5];
    const float* bv = (const float*)d_in[6];
    const float* Wo = (const float*)d_in[7];
    const float* bo = (const float*)d_in[8];
    float* out = (float*)d_out;

    cudaFuncSetAttribute(gemm_h, cudaFuncAttributeMaxDynamicSharedMemorySize, GEMM_SMEM);
    cudaFuncSetAttribute(attn_h, cudaFuncAttributeMaxDynamicSharedMemorySize, ATTN_SMEM);

    const int total4 = NX4 + 4 * NW4;     // 2097152
    conv_h<<<total4 / 256, 256>>>((const float4*)x, (const float4*)Wq,
                                  (const float4*)Wk, (const float4*)Wv,
                                  (const float4*)Wo);

    gemm_h<<<dim3(EE/128, MM/128, 3), 256, GEMM_SMEM>>>(bq, bk, bv, bo, nullptr, -1);
    attn_h<<<dim3(BB*HH, NN/64), 128, ATTN_SMEM>>>();
    gemm_h<<<dim3(EE/128, MM/128, 1), 256, GEMM_SMEM>>>(bq, bk, bv, bo, out, 3);
}

// round 17
// speedup vs baseline: 1.1021x; 1.0160x over previous
#include <cuda_runtime.h>
#include <cuda_fp16.h>
#include <cstdint>

#define BB 2
#define NN 2048
#define EE 1024
#define HH 16
#define DD 64
#define MM (BB*NN)

// Scratch: everything fp16 (same 10-bit mantissa as tf32 -> same accuracy).
__device__ __half g_Xh[MM*EE];          // x
__device__ __half g_Wh[4][EE*EE];       // Wq,Wk,Wv,Wo
__device__ __half g_Q[BB*HH*NN*DD];     // [b,h,n,d]
__device__ __half g_K[BB*HH*NN*DD];
__device__ __half g_V[BB*HH*NN*DD];
__device__ __half g_AOh[BB*NN*EE];      // attn out [b,n,e]

__device__ __forceinline__ void mma_f16(float* d, const uint32_t* a, const uint32_t* b) {
    asm volatile(
        "mma.sync.aligned.m16n8k16.row.col.f32.f16.f16.f32 "
        "{%0,%1,%2,%3}, {%4,%5,%6,%7}, {%8,%9}, {%0,%1,%2,%3};"
        : "+f"(d[0]), "+f"(d[1]), "+f"(d[2]), "+f"(d[3])
        : "r"(a[0]), "r"(a[1]), "r"(a[2]), "r"(a[3]), "r"(b[0]), "r"(b[1]));
}
__device__ __forceinline__ void ldsm4(uint32_t& r0, uint32_t& r1, uint32_t& r2,
                                      uint32_t& r3, uint32_t a) {
    asm volatile("ldmatrix.sync.aligned.m8n8.x4.shared.b16 {%0,%1,%2,%3}, [%4];"
        : "=r"(r0), "=r"(r1), "=r"(r2), "=r"(r3) : "r"(a));
}
__device__ __forceinline__ void ldsm4t(uint32_t& r0, uint32_t& r1, uint32_t& r2,
                                       uint32_t& r3, uint32_t a) {
    asm volatile("ldmatrix.sync.aligned.m8n8.x4.trans.shared.b16 {%0,%1,%2,%3}, [%4];"
        : "=r"(r0), "=r"(r1), "=r"(r2), "=r"(r3) : "r"(a));
}
__device__ __forceinline__ void cpa16(uint32_t s, const void* g) {
    asm volatile("cp.async.cg.shared.global [%0], [%1], 16;" :: "r"(s), "l"(g));
}
__device__ __forceinline__ void cp_commit() { asm volatile("cp.async.commit_group;"); }
template<int N> __device__ __forceinline__ void cp_wait() {
    asm volatile("cp.async.wait_group %0;" :: "n"(N));
}
__device__ __forceinline__ uint32_t pack_h2(float lo, float hi) {
    __half2 h = __floats2half2_rn(lo, hi);
    return *reinterpret_cast<uint32_t*>(&h);
}
__device__ __forceinline__ uint32_t ex2h2(uint32_t x) {   // 2 exps per MUFU op
    uint32_t r;
    asm("ex2.approx.f16x2 %0, %1;" : "=r"(r) : "r"(x));
    return r;
}
__device__ __forceinline__ __half2 u2h2(uint32_t u) {
    __half2 h; *reinterpret_cast<uint32_t*>(&h) = u; return h;
}

// ---------------------------------------------------------------------------
// Fused fp32 -> fp16 convert: x (1M float4) + 4 W's (256K float4 each).
// ---------------------------------------------------------------------------
#define NX4 (MM*EE/4)       // 1048576
#define NW4 (EE*EE/4)       // 262144
__global__ __launch_bounds__(256)
void conv_h(const float4* __restrict__ x,  const float4* __restrict__ w0,
            const float4* __restrict__ w1, const float4* __restrict__ w2,
            const float4* __restrict__ w3)
{
    int i = blockIdx.x * 256 + threadIdx.x;
    const float4* src; __half* dst; int off;
    if (i < NX4) { src = x; dst = g_Xh; off = i; }
    else {
        int k = i - NX4;
        int j = k >> 18;            // NW4 = 2^18
        off = k & (NW4 - 1);
        src = (j == 0) ? w0 : (j == 1) ? w1 : (j == 2) ? w2 : w3;
        dst = g_Wh[j];
    }
    float4 v = src[off];
    __half2* d2 = (__half2*)(dst + (size_t)off * 4);
    d2[0] = __floats2half2_rn(v.x, v.y);
    d2[1] = __floats2half2_rn(v.z, v.w);
}

// ---------------------------------------------------------------------------
// fp16 GEMM (R12 structure): 128x128 tiles, BK=64, 256 thr, 8 warps of 32x64,
// 3-stage cp.async, ldmatrix, single sync per k-iter.
// __launch_bounds__(256,2): raises ptxas reg cap to 128 (occupancy is
// smem-capped at 2 blocks anyway) -> freer load hoisting. (R8 lesson inverted.)
// ---------------------------------------------------------------------------
#define GRS 72                    // smem row stride in halves (64 + 8 pad)
#define GSTH (128*GRS)            // 9216 halves per stage per matrix
#define GEMM_SMEM (6*GSTH*2)      // 110592 B

__global__ __launch_bounds__(256, 2)
void gemm_h(const float* __restrict__ b0p, const float* __restrict__ b1p,
            const float* __restrict__ b2p, const float* __restrict__ b3p,
            float* __restrict__ outp, int target)
{
    const int tgt = (target < 0) ? (int)blockIdx.z : target;
    const __half* __restrict__ X = (tgt == 3) ? g_AOh : g_Xh;
    const __half* __restrict__ W = g_Wh[tgt];
    const float* __restrict__ bias = (tgt == 0) ? b0p : (tgt == 1) ? b1p : (tgt == 2) ? b2p : b3p;

    extern __shared__ __align__(16) __half smh[];
    const uint32_t sbA = (uint32_t)__cvta_generic_to_shared(smh);
    const uint32_t sbW = sbA + 3 * GSTH * 2;

    const int tid = threadIdx.x;
    const int warp = tid >> 5, lane = tid & 31;
    const int g = lane >> 2, t = lane & 3;
    const int m0 = blockIdx.y * 128, n0 = blockIdx.x * 128;
    const int wm = (warp >> 1) * 32, wn = (warp & 1) * 64;

    // ldmatrix per-lane address components
    const int a_row = wm + (lane & 7) + ((lane >> 3) & 1) * 8;  // + mi*16
    const int a_k   = (lane >> 4) * 8;                          // + ks*16
    const int b_row = wn + (lane & 7) + (lane >> 4) * 8;        // + ntp*16
    const int b_k   = ((lane >> 3) & 1) * 8;                    // + ks*16

    float acc[2][8][4];
    #pragma unroll
    for (int i = 0; i < 2; i++)
        #pragma unroll
        for (int j = 0; j < 8; j++)
            #pragma unroll
            for (int k = 0; k < 4; k++) acc[i][j][k] = 0.f;

    // per stage per matrix: 128 rows x 64 halves = 1024 chunks of 16B; 4/thread
    auto issue = [&](int s, int kk) {
        #pragma unroll
        for (int i = 0; i < 4; i++) {
            const int idx = tid + i * 256;
            const int r = idx >> 3, c = (idx & 7) * 8;
            cpa16(sbA + (uint32_t)(s * GSTH + r * GRS + c) * 2,
                  X + (size_t)(m0 + r) * EE + kk * 64 + c);
            cpa16(sbW + (uint32_t)(s * GSTH + r * GRS + c) * 2,
                  W + (size_t)(n0 + r) * EE + kk * 64 + c);
        }
        cp_commit();
    };

    issue(0, 0);
    issue(1, 1);

    for (int kt = 0; kt < 16; kt++) {
        const int buf = kt % 3;
        if (kt < 15) cp_wait<1>(); else cp_wait<0>();
        __syncthreads();
        if (kt + 2 < 16) issue((kt + 2) % 3, kt + 2);

        const uint32_t abase = sbA + (uint32_t)(buf * GSTH) * 2;
        const uint32_t wbase = sbW + (uint32_t)(buf * GSTH) * 2;
        #pragma unroll
        for (int ks = 0; ks < 4; ks++) {
            uint32_t af[2][4];
            ldsm4(af[0][0], af[0][1], af[0][2], af[0][3],
                  abase + (uint32_t)(a_row * GRS + ks * 16 + a_k) * 2);
            ldsm4(af[1][0], af[1][1], af[1][2], af[1][3],
                  abase + (uint32_t)((a_row + 16) * GRS + ks * 16 + a_k) * 2);
            #pragma unroll
            for (int ntp = 0; ntp < 4; ntp++) {
                uint32_t b0, b1, b2, b3;
                ldsm4(b0, b1, b2, b3,
                      wbase + (uint32_t)((b_row + ntp * 16) * GRS + ks * 16 + b_k) * 2);
                uint32_t bfa[2] = {b0, b1}, bfb[2] = {b2, b3};
                mma_f16(acc[0][2 * ntp],     af[0], bfa);
                mma_f16(acc[1][2 * ntp],     af[1], bfa);
                mma_f16(acc[0][2 * ntp + 1], af[0], bfb);
                mma_f16(acc[1][2 * ntp + 1], af[1], bfb);
            }
        }
        // no trailing sync: next iter's top barrier fences the stage reuse
    }

    __half* dstQKV = (tgt == 0) ? g_Q : (tgt == 1) ? g_K : g_V;
    #pragma unroll
    for (int mi = 0; mi < 2; mi++) {
        #pragma unroll
        for (int nt = 0; nt < 8; nt++) {
            const int rbase = m0 + wm + mi * 16 + g;
            const int cbase = n0 + wn + nt * 8 + 2 * t;
            #pragma unroll
            for (int hh = 0; hh < 2; hh++) {
                const int m = rbase + hh * 8;
                const float v0 = acc[mi][nt][2 * hh + 0] + bias[cbase + 0];
                const float v1 = acc[mi][nt][2 * hh + 1] + bias[cbase + 1];
                if (tgt == 3) {
                    outp[m * EE + cbase + 0] = v0;
                    outp[m * EE + cbase + 1] = v1;
                } else {
                    const int b = m >> 11;
                    const int n = m & (NN - 1);
                    const int h = cbase >> 6;
                    const int d = cbase & (DD - 1);
                    *(__half2*)&dstQKV[((b * HH + h) * NN + n) * DD + d] =
                        __floats2half2_rn(v0, v1);
                }
            }
        }
    }
}

// ---------------------------------------------------------------------------
// Flash attention: 128-QUERY blocks (8 warps, 256 thr), 64-key tiles,
// 3-stage cp.async, one barrier/tile, fp16x2 exp, register P-reuse.
// Each K/V tile feeds 8 warps -> half the global K/V traffic of the 64-query
// version. smem (halves): K 3x4608 @0; V 3x4608 @13824; Q 9216 @27648.
// Total 73728 B -> 2 blocks/SM (16 warps).
// ---------------------------------------------------------------------------
#define KSTAGE_H 4608
#define VBASE_H  13824
#define QBASE_H  27648
#define ATTN_SMEM ((QBASE_H + 9216) * 2)   // 73728 B

__global__ __launch_bounds__(256, 2)
void attn_h()
{
    extern __shared__ __align__(16) __half smh[];
    const uint32_t sb = (uint32_t)__cvta_generic_to_shared(smh);

    const int bh = blockIdx.x;
    const int q0 = blockIdx.y * 128;
    const int tid = threadIdx.x, warp = tid >> 5, lane = tid & 31;
    const int g = lane >> 2, t = lane & 3;
    const float L2E = 1.4426950408889634f;

    const __half* __restrict__ Qp = g_Q + (size_t)bh * NN * DD;
    const __half* __restrict__ Kp = g_K + (size_t)bh * NN * DD;
    const __half* __restrict__ Vp = g_V + (size_t)bh * NN * DD;

    // K/V tile = 64 rows x 64 halves = 512 x 16B chunks; 2 per thread
    auto issueK = [&](int s, int kk) {
        const uint32_t off = sb + (uint32_t)(s * KSTAGE_H) * 2;
        #pragma unroll
        for (int i = 0; i < 2; i++) {
            const int idx = tid + i * 256;
            const int r = idx >> 3, c = (idx & 7) * 8;
            cpa16(off + (uint32_t)(r * 72 + c) * 2, Kp + (size_t)(kk * 64 + r) * DD + c);
        }
    };
    auto issueV = [&](int s, int kk) {
        const uint32_t off = sb + (uint32_t)(VBASE_H + s * KSTAGE_H) * 2;
        #pragma unroll
        for (int i = 0; i < 2; i++) {
            const int idx = tid + i * 256;
            const int r = idx >> 3, c = (idx & 7) * 8;
            cpa16(off + (uint32_t)(r * 72 + c) * 2, Vp + (size_t)(kk * 64 + r) * DD + c);
        }
    };

    // Prologue: Q (128 rows) -> staging; tiles 0,1 -> stages 0,1
    {
        const uint32_t qoff = sb + (uint32_t)QBASE_H * 2;
        #pragma unroll
        for (int i = 0; i < 4; i++) {
            const int idx = tid + i * 256;
            const int r = idx >> 3, c = (idx & 7) * 8;
            cpa16(qoff + (uint32_t)(r * 72 + c) * 2, Qp + (size_t)(q0 + r) * DD + c);
        }
        cp_commit();
        issueK(0, 0); issueV(0, 0); cp_commit();
        issueK(1, 1); issueV(1, 1); cp_commit();
    }
    cp_wait<2>();
    __syncthreads();

    // hoist Q a-fragments via ldmatrix (4 k-steps of 16); warp owns 16 rows
    const int a_row = warp * 16 + (lane & 7) + ((lane >> 3) & 1) * 8;
    const int a_k   = (lane >> 4) * 8;
    uint32_t qa[4][4];
    {
        const uint32_t qbase = sb + (uint32_t)QBASE_H * 2;
        #pragma unroll
        for (int ks = 0; ks < 4; ks++)
            ldsm4(qa[ks][0], qa[ks][1], qa[ks][2], qa[ks][3],
                  qbase + (uint32_t)(a_row * 72 + ks * 16 + a_k) * 2);
    }

    float O[8][4];
    #pragma unroll
    for (int i = 0; i < 8; i++)
        #pragma unroll
        for (int j = 0; j < 4; j++) O[i][j] = 0.f;
    float m1 = -1e30f, m2 = -1e30f, l1 = 0.f, l2 = 0.f;

    // ldmatrix lane address components
    const int kb_row = (lane & 7) + (lane >> 4) * 8;        // + ntp*16 (K b-frags)
    const int kb_k   = ((lane >> 3) & 1) * 8;               // + ks*16
    const int llo = lane & 7, sel = lane >> 3;
    const uint32_t vlane = (uint32_t)(((sel & 1) * 8 + llo) * 72 + (sel >> 1) * 8) * 2;

    for (int kt = 0; kt < 32; kt++) {
        const int buf = kt % 3;
        if (kt < 31) cp_wait<1>(); else cp_wait<0>();
        __syncthreads();     // the ONLY block barrier per tile
        if (kt + 2 < 32) { issueK((kt + 2) % 3, kt + 2); issueV((kt + 2) % 3, kt + 2); cp_commit(); }

        const uint32_t kbase  = sb + (uint32_t)(buf * KSTAGE_H) * 2;
        const uint32_t vstage = sb + (uint32_t)(VBASE_H + buf * KSTAGE_H) * 2;

        // S = Q K^T  (16 x 64 per warp), k-steps of 16
        float S[8][4];
        #pragma unroll
        for (int i = 0; i < 8; i++)
            #pragma unroll
            for (int j = 0; j < 4; j++) S[i][j] = 0.f;

        #pragma unroll
        for (int ks = 0; ks < 4; ks++) {
            #pragma unroll
            for (int ntp = 0; ntp < 4; ntp++) {
                uint32_t b0, b1, b2, b3;
                ldsm4(b0, b1, b2, b3,
                      kbase + (uint32_t)((kb_row + ntp * 16) * 72 + ks * 16 + kb_k) * 2);
                uint32_t bfa[2] = {b0, b1}, bfb[2] = {b2, b3};
                mma_f16(S[2 * ntp],     qa[ks], bfa);
                mma_f16(S[2 * ntp + 1], qa[ks], bfb);
            }
        }

        // online softmax (exp in fp16x2)
        float rmax1 = -1e30f, rmax2 = -1e30f;
        #pragma unroll
        for (int nt = 0; nt < 8; nt++) {
            rmax1 = fmaxf(rmax1, fmaxf(S[nt][0], S[nt][1]));
            rmax2 = fmaxf(rmax2, fmaxf(S[nt][2], S[nt][3]));
        }
        rmax1 = fmaxf(rmax1, __shfl_xor_sync(0xffffffff, rmax1, 1));
        rmax1 = fmaxf(rmax1, __shfl_xor_sync(0xffffffff, rmax1, 2));
        rmax2 = fmaxf(rmax2, __shfl_xor_sync(0xffffffff, rmax2, 1));
        rmax2 = fmaxf(rmax2, __shfl_xor_sync(0xffffffff, rmax2, 2));

        const float mn1 = fmaxf(m1, rmax1);
        const float mn2 = fmaxf(m2, rmax2);
        const float cr1 = __expf(m1 - mn1);
        const float cr2 = __expf(m2 - mn2);
        const float bb1 = mn1 * L2E;
        const float bb2 = mn2 * L2E;

        uint32_t p1[8], p2[8];
        __half2 hs1 = __floats2half2_rn(0.f, 0.f);
        __half2 hs2 = hs1;
        #pragma unroll
        for (int nt = 0; nt < 8; nt++) {
            uint32_t u1 = pack_h2(fmaf(S[nt][0], L2E, -bb1), fmaf(S[nt][1], L2E, -bb1));
            uint32_t u2 = pack_h2(fmaf(S[nt][2], L2E, -bb2), fmaf(S[nt][3], L2E, -bb2));
            p1[nt] = ex2h2(u1);
            p2[nt] = ex2h2(u2);
            hs1 = __hadd2(hs1, u2h2(p1[nt]));
            hs2 = __hadd2(hs2, u2h2(p2[nt]));
        }
        float rs1 = __low2float(hs1) + __high2float(hs1);
        float rs2 = __low2float(hs2) + __high2float(hs2);
        rs1 += __shfl_xor_sync(0xffffffff, rs1, 1);
        rs1 += __shfl_xor_sync(0xffffffff, rs1, 2);
        rs2 += __shfl_xor_sync(0xffffffff, rs2, 1);
        rs2 += __shfl_xor_sync(0xffffffff, rs2, 2);

        l1 = l1 * cr1 + rs1;
        l2 = l2 * cr2 + rs2;
        m1 = mn1; m2 = mn2;

        if (cr1 < 1.0f || cr2 < 1.0f) {      // skip rescale when max unchanged
            #pragma unroll
            for (int nt = 0; nt < 8; nt++) {
                O[nt][0] *= cr1; O[nt][1] *= cr1;
                O[nt][2] *= cr2; O[nt][3] *= cr2;
            }
        }

        // O += P V  — P a-frags directly from the packed exp registers
        #pragma unroll
        for (int ks = 0; ks < 4; ks++) {
            uint32_t pa[4] = { p1[2 * ks], p2[2 * ks], p1[2 * ks + 1], p2[2 * ks + 1] };
            #pragma unroll
            for (int p = 0; p < 4; p++) {
                uint32_t b0, b1, b2, b3;
                ldsm4t(b0, b1, b2, b3, vstage + vlane + ks * 2304 + p * 32);
                uint32_t bA[2] = {b0, b1}, bB[2] = {b2, b3};
                mma_f16(O[2 * p],     pa, bA);
                mma_f16(O[2 * p + 1], pa, bB);
            }
        }
    }

    // epilogue: softmax norm + reference's /sqrt(E)=32; write fp16
    const int b = bh / HH, h = bh % HH;
    const int q1 = q0 + warp * 16 + g;
    const int q2 = q1 + 8;
    const float i1 = 1.0f / (l1 * 32.0f);
    const float i2 = 1.0f / (l2 * 32.0f);
    __half2* d1 = (__half2*)(g_AOh + ((size_t)(b * NN + q1)) * EE + h * DD);
    __half2* d2 = (__half2*)(g_AOh + ((size_t)(b * NN + q2)) * EE + h * DD);
    #pragma unroll
    for (int nt = 0; nt < 8; nt++) {
        d1[nt * 4 + t] = __floats2half2_rn(O[nt][0] * i1, O[nt][1] * i1);
        d2[nt * 4 + t] = __floats2half2_rn(O[nt][2] * i2, O[nt][3] * i2);
    }
}

// ---------------------------------------------------------------------------
extern "C" void kernel_launch(void* const* d_in, const int* in_sizes, int n_in,
                              void* d_out, int out_size)
{
    const float* x  = (const float*)d_in[0];
    const float* Wq = (const float*)d_in[1];
    const float* bq = (const float*)d_in[2];
    const float* Wk = (const float*)d_in[3];
    const float* bk = (const float*)d_in[4];
    const float* Wv = (const float*)d_in[5];
    const float* bv = (const float*)d_in[6];
    const float* Wo = (const float*)d_in[7];
    const float* bo = (const float*)d_in[8];
    float* out = (float*)d_out;

    cudaFuncSetAttribute(gemm_h, cudaFuncAttributeMaxDynamicSharedMemorySize, GEMM_SMEM);
    cudaFuncSetAttribute(attn_h, cudaFuncAttributeMaxDynamicSharedMemorySize, ATTN_SMEM);

    const int total4 = NX4 + 4 * NW4;     // 2097152
    conv_h<<<total4 / 256, 256>>>((const float4*)x, (const float4*)Wq,
                                  (const float4*)Wk, (const float4*)Wv,
                                  (const float4*)Wo);

    gemm_h<<<dim3(EE/128, MM/128, 3), 256, GEMM_SMEM>>>(bq, bk, bv, bo, nullptr, -1);
    attn_h<<<dim3(BB*HH, NN/128), 256, ATTN_SMEM>>>();
    gemm_h<<<dim3(EE/128, MM/128, 1), 256, GEMM_SMEM>>>(bq, bk, bv, bo, out, 3);
}